// round 7
// baseline (speedup 1.0000x reference)
#include <cuda_runtime.h>
#include <cstdint>
#include <cstddef>

// ---------------------------------------------------------------------------
// SSIM loss, fused single kernel (packed f32x2, UNCONDITIONAL scatter):
//   5 separable 11-tap Gaussian convs (p, t, p^2, t^2, p*t) + SSIM map + mean.
// Block: 128 output cols x 64 output rows; 64 threads, each owns 2 adjacent
// columns packed in one f32x2 pair. Raw rows double-buffered via cp.async.
// Vertical conv: register-rolling 11-slot f32x2 accumulator ring.
//   - scatter is unconditional: k=0 tap OVERWRITES its slot (mul2), which is
//     always the slot finalized on the previous row -> no zeroing, no masks,
//     no branches; garbage out-rows are overwritten or bit-masked at finalize
//   - finalize mask is per-group uniform (1 AND per row)
//   - one MUFU.RCP per finalize: (n0*d1 + n1*d0) * rcp(d0*d1)
// ---------------------------------------------------------------------------

#define IMG_H 512
#define IMG_W 512
#define NBATCH 32
#define THREADS 64
#define TW 128              // output cols per block
#define RH 64               // output rows per block
#define NIN (RH + 10)       // 74 input rows touched
#define RAWW 144            // staged row width in floats ([x0-8, x0+136))
#define NV4 (RAWW / 4)      // 36 float4 per row
#define GROUP 11
#define NBLOCKS ((IMG_W / TW) * (IMG_H / RH) * NBATCH)   // 1024

using ull = unsigned long long;

__device__ double   g_accum = 0.0;
__device__ unsigned g_count = 0;

// ---- packed f32x2 helpers (sm_103a) ----
__device__ __forceinline__ ull pack2(float lo, float hi) {
    ull r; asm("mov.b64 %0, {%1, %2};" : "=l"(r) : "f"(lo), "f"(hi)); return r;
}
__device__ __forceinline__ ull fma2(ull a, ull b, ull c) {
    ull r; asm("fma.rn.f32x2 %0, %1, %2, %3;" : "=l"(r) : "l"(a), "l"(b), "l"(c)); return r;
}
__device__ __forceinline__ ull mul2(ull a, ull b) {
    ull r; asm("mul.rn.f32x2 %0, %1, %2;" : "=l"(r) : "l"(a), "l"(b)); return r;
}
__device__ __forceinline__ float2 unpk2(ull v) {
    float2 f; asm("mov.b64 {%0, %1}, %2;" : "=f"(f.x), "=f"(f.y) : "l"(v)); return f;
}

__device__ __forceinline__ unsigned smem_u32(const void* p) {
    return (unsigned)__cvta_generic_to_shared(p);
}
__device__ __forceinline__ void cp_async16(unsigned saddr, const void* gaddr, int srcsize) {
    asm volatile("cp.async.ca.shared.global [%0], [%1], 16, %2;\n"
                 :: "r"(saddr), "l"(gaddr), "r"(srcsize));
}
__device__ __forceinline__ void cp_commit() { asm volatile("cp.async.commit_group;\n" ::: "memory"); }
__device__ __forceinline__ void cp_wait1()  { asm volatile("cp.async.wait_group 1;\n" ::: "memory"); }
__device__ __forceinline__ void cp_wait0()  { asm volatile("cp.async.wait_group 0;\n" ::: "memory"); }

// Issue cp.async for one 11-row group of both tensors into sbuf.
__device__ __forceinline__ void load_group(float* sbuf,  // [2][GROUP][RAWW]
                                           const float* __restrict__ P,
                                           const float* __restrict__ T,
                                           int g, int x0, int y0) {
    const int total = 2 * GROUP * NV4;  // 792
    for (int idx = threadIdx.x; idx < total; idx += THREADS) {
        int tsel = idx / (GROUP * NV4);
        int rem  = idx % (GROUP * NV4);
        int r    = rem / NV4;
        int cv   = rem % NV4;
        int i    = g * GROUP + r;
        int ir   = y0 - 5 + i;
        int c0   = x0 - 8 + cv * 4;
        bool ok = (i < NIN) && ((unsigned)ir < (unsigned)IMG_H) && ((unsigned)c0 < (unsigned)IMG_W);
        const float* src = tsel ? T : P;
        const float* gp  = ok ? (src + (size_t)ir * IMG_W + c0) : src;
        unsigned sa = smem_u32(sbuf + (tsel * GROUP + r) * RAWW + cv * 4);
        cp_async16(sa, gp, ok ? 16 : 0);
    }
}

// One input row. J compile-time; finmask (0 or ~0u) hoisted per group.
template<int J>
__device__ __forceinline__ void row_body(const float* __restrict__ basep,
                                         const float* __restrict__ baset,
                                         int tid2, ull (&acc)[5][GROUP],
                                         const ull (&W2)[GROUP],
                                         unsigned finmask, float& tsum) {
    const float C1f = 1e-4f;   // 0.01^2
    const float C2f = 9e-4f;   // 0.03^2

    // ---- load aligned pairs: staged[tid2+2 .. tid2+15] ----
    ull Ap[7], At[7];
    float pf[14], tf[14];
    #pragma unroll
    for (int m = 0; m < 7; ++m) {
        Ap[m] = *(const ull*)(basep + J * RAWW + tid2 + 2 + 2 * m);
        At[m] = *(const ull*)(baset + J * RAWW + tid2 + 2 + 2 * m);
        float2 a = unpk2(Ap[m]); pf[2 * m] = a.x; pf[2 * m + 1] = a.y;
        float2 c = unpk2(At[m]); tf[2 * m] = c.x; tf[2 * m + 1] = c.y;
    }

    // ---- horizontal conv, packed column pair (full 11 taps) ----
    ull h0, h1, h2, h3, h4;
    #pragma unroll
    for (int k = 0; k < 11; ++k) {
        ull Pk, Tk;
        if (k & 1) { Pk = Ap[(k + 1) / 2]; Tk = At[(k + 1) / 2]; }
        else       { Pk = pack2(pf[k + 1], pf[k + 2]);
                     Tk = pack2(tf[k + 1], tf[k + 2]); }
        ull P2k = mul2(Pk, Pk);
        ull T2k = mul2(Tk, Tk);
        ull PTk = mul2(Pk, Tk);
        if (k == 0) {
            h0 = mul2(Pk,  W2[0]);
            h1 = mul2(Tk,  W2[0]);
            h2 = mul2(P2k, W2[0]);
            h3 = mul2(T2k, W2[0]);
            h4 = mul2(PTk, W2[0]);
        } else {
            h0 = fma2(Pk,  W2[k], h0);
            h1 = fma2(Tk,  W2[k], h1);
            h2 = fma2(P2k, W2[k], h2);
            h3 = fma2(T2k, W2[k], h3);
            h4 = fma2(PTk, W2[k], h4);
        }
    }
    ull h[5] = { h0, h1, h2, h3, h4 };

    // ---- vertical scatter: ALL 11 taps, unconditional ----
    // k=0 overwrites (mul2): its slot is exactly the one finalized last row.
    #pragma unroll
    for (int k = 0; k < 11; ++k) {
        const int s = (J - k + 11) % 11;                    // compile-time
        #pragma unroll
        for (int ch = 0; ch < 5; ++ch) {
            if (k == 0) acc[ch][s] = mul2(h[ch], W2[0]);
            else        acc[ch][s] = fma2(h[ch], W2[k], acc[ch][s]);
        }
    }

    // ---- finalize slot f (output row i-10); bit-masked by finmask ----
    {
        const int f = (J + 1) % 11;                         // compile-time
        float2 mu1v = unpk2(acc[0][f]);
        float2 mu2v = unpk2(acc[1][f]);
        float2 ep2v = unpk2(acc[2][f]);
        float2 et2v = unpk2(acc[3][f]);
        float2 eptv = unpk2(acc[4][f]);
        float n[2], d[2];
        #pragma unroll
        for (int v = 0; v < 2; ++v) {
            float mu1 = v ? mu1v.y : mu1v.x;
            float mu2 = v ? mu2v.y : mu2v.x;
            float ep2 = v ? ep2v.y : ep2v.x;
            float et2 = v ? et2v.y : et2v.x;
            float ept = v ? eptv.y : eptv.x;
            float mu1s = mu1 * mu1;
            float mu2s = mu2 * mu2;
            float mu12 = mu1 * mu2;
            float s1  = ep2 - mu1s;
            float s2  = et2 - mu2s;
            float s12 = ept - mu12;
            n[v] = fmaf(2.f, mu12, C1f) * fmaf(2.f, s12, C2f);
            d[v] = (mu1s + mu2s + C1f) * (s1 + s2 + C2f);
        }
        // one reciprocal: n0/d0 + n1/d1 = (n0*d1 + n1*d0) / (d0*d1)
        float num = n[0] * d[1] + n[1] * d[0];
        float rden;
        asm("rcp.approx.f32 %0, %1;" : "=f"(rden) : "f"(d[0] * d[1]));
        float vsum = num * rden;
        unsigned vb = __float_as_uint(vsum) & finmask;      // NaN/inf safe
        tsum += __uint_as_float(vb);
    }
}

__global__ void __launch_bounds__(THREADS, 6)
ssim_main(const float* __restrict__ pred, const float* __restrict__ targ,
          float* __restrict__ out) {
    __shared__ __align__(16) float sraw[2][2][GROUP][RAWW];   // 24.75 KB
    __shared__ float sred[THREADS / 32];
    __shared__ bool amLast;

    const int x0 = blockIdx.x * TW;
    const int y0 = blockIdx.y * RH;
    const int b  = blockIdx.z;
    const float* P = pred + (size_t)b * (IMG_H * IMG_W);
    const float* T = targ + (size_t)b * (IMG_H * IMG_W);
    const int tid  = threadIdx.x;
    const int tid2 = 2 * tid;

    // 1D Gaussian weights (normalized), packed and replicated.
    const float Wc[11] = {
        1.4867195e-06f, 1.3383023e-04f, 4.4318484e-03f, 5.3990967e-02f,
        2.4197073e-01f, 3.9894228e-01f, 2.4197073e-01f, 5.3990967e-02f,
        4.4318484e-03f, 1.3383023e-04f, 1.4867195e-06f };
    ull W2[11];
    #pragma unroll
    for (int k = 0; k < 11; ++k) W2[k] = pack2(Wc[k], Wc[k]);

    // Rolling accumulator ring; init not strictly needed (k=0 overwrites and
    // pre-first-use garbage is bit-masked), but keep it defined.
    ull acc[5][GROUP];
    #pragma unroll
    for (int c = 0; c < 5; ++c)
        #pragma unroll
        for (int s = 0; s < GROUP; ++s) acc[c][s] = 0ull;

    float tsum = 0.f;

    float* B0p = &sraw[0][0][0][0]; float* B0t = &sraw[0][1][0][0];
    float* B1p = &sraw[1][0][0][0]; float* B1t = &sraw[1][1][0][0];

    // Prologue: prefetch group 0 into B0
    load_group(B0p, P, T, 0, x0, y0);
    cp_commit();

    // ---- groups 0..5: all 11 rows active (i = 0..65 < NIN) ----
    #pragma unroll 1
    for (int g = 0; g < 6; ++g) {
        float* nbp = ((g + 1) & 1) ? B1p : B0p;
        load_group(nbp, P, T, g + 1, x0, y0);
        cp_commit(); cp_wait1();
        __syncthreads();
        const float* bp = (g & 1) ? B1p : B0p;
        const float* bt = (g & 1) ? B1t : B0t;
        // finmask: out-row i-10 valid iff i >= 10; i = 11g + J.
        unsigned m0 = (g == 0) ? 0u : ~0u;   // rows J=0..9
        row_body<0>(bp, bt, tid2, acc, W2, m0, tsum);
        row_body<1>(bp, bt, tid2, acc, W2, m0, tsum);
        row_body<2>(bp, bt, tid2, acc, W2, m0, tsum);
        row_body<3>(bp, bt, tid2, acc, W2, m0, tsum);
        row_body<4>(bp, bt, tid2, acc, W2, m0, tsum);
        row_body<5>(bp, bt, tid2, acc, W2, m0, tsum);
        row_body<6>(bp, bt, tid2, acc, W2, m0, tsum);
        row_body<7>(bp, bt, tid2, acc, W2, m0, tsum);
        row_body<8>(bp, bt, tid2, acc, W2, m0, tsum);
        row_body<9>(bp, bt, tid2, acc, W2, m0, tsum);
        row_body<10>(bp, bt, tid2, acc, W2, ~0u, tsum);   // i=11g+10 >= 10 always
        __syncthreads();
    }

    // ---- group 6: rows 0..7 only (i = 66..73); data in B0 (6 & 1 == 0) ----
    cp_wait0();
    __syncthreads();
    row_body<0>(B0p, B0t, tid2, acc, W2, ~0u, tsum);
    row_body<1>(B0p, B0t, tid2, acc, W2, ~0u, tsum);
    row_body<2>(B0p, B0t, tid2, acc, W2, ~0u, tsum);
    row_body<3>(B0p, B0t, tid2, acc, W2, ~0u, tsum);
    row_body<4>(B0p, B0t, tid2, acc, W2, ~0u, tsum);
    row_body<5>(B0p, B0t, tid2, acc, W2, ~0u, tsum);
    row_body<6>(B0p, B0t, tid2, acc, W2, ~0u, tsum);
    row_body<7>(B0p, B0t, tid2, acc, W2, ~0u, tsum);

    // ---- block reduction -> global double accumulator ----
    float s = tsum;
    #pragma unroll
    for (int off = 16; off; off >>= 1)
        s += __shfl_xor_sync(0xffffffffu, s, off);
    if ((tid & 31) == 0) sred[tid >> 5] = s;
    __syncthreads();
    if (tid == 0) {
        atomicAdd(&g_accum, (double)(sred[0] + sred[1]));
        __threadfence();
        unsigned prev = atomicAdd(&g_count, 1u);
        amLast = (prev == (unsigned)(NBLOCKS - 1));
    }
    __syncthreads();

    // ---- last block finalizes and resets state for the next graph replay ----
    if (amLast && tid == 0) {
        double total = atomicAdd(&g_accum, 0.0);   // coherent read
        out[0] = (float)(1.0 - total * (1.0 / (double)(NBATCH * IMG_H * IMG_W)));
        g_accum = 0.0;
        g_count = 0u;
    }
}

extern "C" void kernel_launch(void* const* d_in, const int* in_sizes, int n_in,
                              void* d_out, int out_size) {
    const float* pred = (const float*)d_in[0];
    const float* targ = (const float*)d_in[1];
    // d_in[2] (window) is a fixed Gaussian; weights are baked as immediates.
    (void)in_sizes; (void)n_in; (void)out_size;

    dim3 grid(IMG_W / TW, IMG_H / RH, NBATCH);   // 4 x 8 x 32 = 1024 blocks
    ssim_main<<<grid, THREADS>>>(pred, targ, (float*)d_out);
}

// round 8
// speedup vs baseline: 1.1474x; 1.1474x over previous
#include <cuda_runtime.h>
#include <cstdint>
#include <cstddef>

// ---------------------------------------------------------------------------
// SSIM loss, fully fused single kernel (packed f32x2 + guarded scatter, the
// measured-best R2/R4 structure) with occupancy raised to 5 blocks/SM:
//   5 separable 11-tap Gaussian convs (p, t, p^2, t^2, p*t) + SSIM map + mean.
// Block: 128 output cols x 64 output rows; 64 threads, each owns 2 adjacent
// columns packed into one f32x2 register pair.
// Raw rows streamed via double-buffered cp.async (zfill = SAME zero pad).
// Vertical conv: register-rolling 11-slot f32x2 accumulator ring with
// warp-uniform guarded scatter (cheap uniform branches that SKIP work).
// Finalize uses one MUFU.RCP per output pair.
// ---------------------------------------------------------------------------

#define IMG_H 512
#define IMG_W 512
#define NBATCH 32
#define THREADS 64
#define TW 128              // output cols per block
#define RH 64               // output rows per block
#define NIN (RH + 10)       // 74 input rows touched
#define RAWW 144            // staged row width in floats ([x0-8, x0+136))
#define NV4 (RAWW / 4)      // 36 float4 per row
#define GROUP 11
#define NGROUPS ((NIN + GROUP - 1) / GROUP)   // 7
#define NBLOCKS ((IMG_W / TW) * (IMG_H / RH) * NBATCH)   // 1024

using ull = unsigned long long;

__device__ double   g_accum = 0.0;
__device__ unsigned g_count = 0;

// ---- packed f32x2 helpers (sm_103a) ----
__device__ __forceinline__ ull pack2(float lo, float hi) {
    ull r; asm("mov.b64 %0, {%1, %2};" : "=l"(r) : "f"(lo), "f"(hi)); return r;
}
__device__ __forceinline__ ull fma2(ull a, ull b, ull c) {
    ull r; asm("fma.rn.f32x2 %0, %1, %2, %3;" : "=l"(r) : "l"(a), "l"(b), "l"(c)); return r;
}
__device__ __forceinline__ ull mul2(ull a, ull b) {
    ull r; asm("mul.rn.f32x2 %0, %1, %2;" : "=l"(r) : "l"(a), "l"(b)); return r;
}
__device__ __forceinline__ float2 unpk2(ull v) {
    float2 f; asm("mov.b64 {%0, %1}, %2;" : "=f"(f.x), "=f"(f.y) : "l"(v)); return f;
}

__device__ __forceinline__ unsigned smem_u32(const void* p) {
    return (unsigned)__cvta_generic_to_shared(p);
}
__device__ __forceinline__ void cp_async16(unsigned saddr, const void* gaddr, int srcsize) {
    asm volatile("cp.async.ca.shared.global [%0], [%1], 16, %2;\n"
                 :: "r"(saddr), "l"(gaddr), "r"(srcsize));
}
__device__ __forceinline__ void cp_commit() { asm volatile("cp.async.commit_group;\n" ::: "memory"); }
__device__ __forceinline__ void cp_wait1()  { asm volatile("cp.async.wait_group 1;\n" ::: "memory"); }
__device__ __forceinline__ void cp_wait0()  { asm volatile("cp.async.wait_group 0;\n" ::: "memory"); }

// Issue cp.async for one 11-row group of both tensors into sbuf.
__device__ __forceinline__ void load_group(float* sbuf,  // [2][GROUP][RAWW]
                                           const float* __restrict__ P,
                                           const float* __restrict__ T,
                                           int g, int x0, int y0) {
    const int total = 2 * GROUP * NV4;  // 792
    for (int idx = threadIdx.x; idx < total; idx += THREADS) {
        int tsel = idx / (GROUP * NV4);
        int rem  = idx % (GROUP * NV4);
        int r    = rem / NV4;
        int cv   = rem % NV4;
        int i    = g * GROUP + r;
        int ir   = y0 - 5 + i;
        int c0   = x0 - 8 + cv * 4;
        bool ok = (i < NIN) && ((unsigned)ir < (unsigned)IMG_H) && ((unsigned)c0 < (unsigned)IMG_W);
        const float* src = tsel ? T : P;
        const float* gp  = ok ? (src + (size_t)ir * IMG_W + c0) : src;
        unsigned sa = smem_u32(sbuf + (tsel * GROUP + r) * RAWW + cv * 4);
        cp_async16(sa, gp, ok ? 16 : 0);
    }
}

__global__ void __launch_bounds__(THREADS, 5)
ssim_main(const float* __restrict__ pred, const float* __restrict__ targ,
          float* __restrict__ out) {
    __shared__ __align__(16) float sraw[2][2][GROUP][RAWW];   // 24.75 KB
    __shared__ float sred[THREADS / 32];
    __shared__ bool amLast;

    const int x0 = blockIdx.x * TW;
    const int y0 = blockIdx.y * RH;
    const int b  = blockIdx.z;
    const float* P = pred + (size_t)b * (IMG_H * IMG_W);
    const float* T = targ + (size_t)b * (IMG_H * IMG_W);
    const int tid = threadIdx.x;

    // 1D Gaussian weights (normalized) as compile-time literals.
    const float Wc[11] = {
        1.4867195e-06f, 1.3383023e-04f, 4.4318484e-03f, 5.3990967e-02f,
        2.4197073e-01f, 3.9894228e-01f, 2.4197073e-01f, 5.3990967e-02f,
        4.4318484e-03f, 1.3383023e-04f, 1.4867195e-06f };
    const float C1f = 1e-4f;   // 0.01^2
    const float C2f = 9e-4f;   // 0.03^2

    // Packed (replicated) weights, loop-invariant registers.
    ull W2[11];
    #pragma unroll
    for (int k = 0; k < 11; ++k) W2[k] = pack2(Wc[k], Wc[k]);

    // Rolling vertical accumulators: [channel][ring slot], each = f32x2 col pair.
    ull acc[5][GROUP];
    #pragma unroll
    for (int c = 0; c < 5; ++c)
        #pragma unroll
        for (int s = 0; s < GROUP; ++s) acc[c][s] = 0ull;

    float tsum = 0.f;

    // Prologue: prefetch group 0
    load_group(&sraw[0][0][0][0], P, T, 0, x0, y0);
    cp_commit();

    for (int g = 0; g < NGROUPS; ++g) {
        if (g + 1 < NGROUPS) {
            load_group(&sraw[(g + 1) & 1][0][0][0], P, T, g + 1, x0, y0);
            cp_commit();
            cp_wait1();     // group g complete, group g+1 may be in flight
        } else {
            cp_wait0();
        }
        __syncthreads();

        const float* basep = &sraw[g & 1][0][0][0];
        const float* baset = &sraw[g & 1][1][0][0];

        #pragma unroll
        for (int j = 0; j < GROUP; ++j) {
            int i = g * GROUP + j;
            if (i < NIN) {
                // ---- load aligned pairs: staged[2*tid+2 .. 2*tid+15] ----
                ull Ap[7], At[7];
                float pf[14], tf[14];
                #pragma unroll
                for (int m = 0; m < 7; ++m) {
                    Ap[m] = *(const ull*)(basep + j * RAWW + 2 * tid + 2 + 2 * m);
                    At[m] = *(const ull*)(baset + j * RAWW + 2 * tid + 2 + 2 * m);
                    float2 a = unpk2(Ap[m]); pf[2 * m] = a.x; pf[2 * m + 1] = a.y;
                    float2 c = unpk2(At[m]); tf[2 * m] = c.x; tf[2 * m + 1] = c.y;
                }

                // ---- horizontal conv, packed column pair ----
                // tap k needs pair (x[k+1], x[k+2]); odd k hits an aligned pair.
                ull h0, h1, h2, h3, h4;
                #pragma unroll
                for (int k = 0; k < 11; ++k) {
                    ull Pk, Tk;
                    if (k & 1) { Pk = Ap[(k + 1) / 2]; Tk = At[(k + 1) / 2]; }
                    else       { Pk = pack2(pf[k + 1], pf[k + 2]);
                                 Tk = pack2(tf[k + 1], tf[k + 2]); }
                    ull P2k = mul2(Pk, Pk);
                    ull T2k = mul2(Tk, Tk);
                    ull PTk = mul2(Pk, Tk);
                    if (k == 0) {
                        h0 = mul2(Pk,  W2[0]);
                        h1 = mul2(Tk,  W2[0]);
                        h2 = mul2(P2k, W2[0]);
                        h3 = mul2(T2k, W2[0]);
                        h4 = mul2(PTk, W2[0]);
                    } else {
                        h0 = fma2(Pk,  W2[k], h0);
                        h1 = fma2(Tk,  W2[k], h1);
                        h2 = fma2(P2k, W2[k], h2);
                        h3 = fma2(T2k, W2[k], h3);
                        h4 = fma2(PTk, W2[k], h4);
                    }
                }
                ull h[5] = { h0, h1, h2, h3, h4 };

                // ---- vertical scatter into rolling ring (warp-uniform guards) ----
                // input row i contributes to output oy = i - k with weight Wc[k]
                #pragma unroll
                for (int k = 0; k < 11; ++k) {
                    const int s = (j - k + 11) % 11;     // compile-time
                    bool on = (i >= k) && (i - k < RH);
                    if (on) {
                        #pragma unroll
                        for (int ch = 0; ch < 5; ++ch) {
                            if (k == 0) acc[ch][s] = mul2(h[ch], W2[0]);   // fresh slot
                            else        acc[ch][s] = fma2(h[ch], W2[k], acc[ch][s]);
                        }
                    }
                }

                // ---- finalize output row oy = i - 10 (one rcp per pair) ----
                if (i >= 10) {
                    const int f = (j + 1) % 11;          // compile-time
                    float2 mu1v = unpk2(acc[0][f]);
                    float2 mu2v = unpk2(acc[1][f]);
                    float2 ep2v = unpk2(acc[2][f]);
                    float2 et2v = unpk2(acc[3][f]);
                    float2 eptv = unpk2(acc[4][f]);
                    float n[2], d[2];
                    #pragma unroll
                    for (int v = 0; v < 2; ++v) {
                        float mu1 = v ? mu1v.y : mu1v.x;
                        float mu2 = v ? mu2v.y : mu2v.x;
                        float ep2 = v ? ep2v.y : ep2v.x;
                        float et2 = v ? et2v.y : et2v.x;
                        float ept = v ? eptv.y : eptv.x;
                        float mu1s = mu1 * mu1;
                        float mu2s = mu2 * mu2;
                        float mu12 = mu1 * mu2;
                        float s1  = ep2 - mu1s;
                        float s2  = et2 - mu2s;
                        float s12 = ept - mu12;
                        n[v] = fmaf(2.f, mu12, C1f) * fmaf(2.f, s12, C2f);
                        d[v] = (mu1s + mu2s + C1f) * (s1 + s2 + C2f);
                    }
                    // n0/d0 + n1/d1 = (n0*d1 + n1*d0) * rcp(d0*d1); d > C1*C2 > 0
                    float num = n[0] * d[1] + n[1] * d[0];
                    float rden;
                    asm("rcp.approx.f32 %0, %1;" : "=f"(rden) : "f"(d[0] * d[1]));
                    tsum = fmaf(num, rden, tsum);
                }
            }
        }
        __syncthreads();   // protect buffer (g&1) before next prefetch reuses it
    }

    // ---- block reduction -> global double accumulator ----
    float s = tsum;
    #pragma unroll
    for (int off = 16; off; off >>= 1)
        s += __shfl_xor_sync(0xffffffffu, s, off);
    if ((tid & 31) == 0) sred[tid >> 5] = s;
    __syncthreads();
    if (tid == 0) {
        atomicAdd(&g_accum, (double)(sred[0] + sred[1]));
        __threadfence();
        unsigned prev = atomicAdd(&g_count, 1u);
        amLast = (prev == (unsigned)(NBLOCKS - 1));
    }
    __syncthreads();

    // ---- last block finalizes and resets state for the next graph replay ----
    if (amLast && tid == 0) {
        double total = atomicAdd(&g_accum, 0.0);   // coherent read
        out[0] = (float)(1.0 - total * (1.0 / (double)(NBATCH * IMG_H * IMG_W)));
        g_accum = 0.0;
        g_count = 0u;
    }
}

extern "C" void kernel_launch(void* const* d_in, const int* in_sizes, int n_in,
                              void* d_out, int out_size) {
    const float* pred = (const float*)d_in[0];
    const float* targ = (const float*)d_in[1];
    // d_in[2] (window) is a fixed Gaussian; weights are baked as immediates.
    (void)in_sizes; (void)n_in; (void)out_size;

    dim3 grid(IMG_W / TW, IMG_H / RH, NBATCH);   // 4 x 8 x 32 = 1024 blocks
    ssim_main<<<grid, THREADS>>>(pred, targ, (float*)d_out);
}

// round 9
// speedup vs baseline: 1.2543x; 1.0932x over previous
#include <cuda_runtime.h>
#include <cstdint>
#include <cstddef>

// ---------------------------------------------------------------------------
// SSIM loss, fused single kernel — 4-channel sum/difference formulation:
//   with a = p+t, b = p-t, SSIM needs only conv(a), conv(b), conv(a^2),
//   conv(b^2):  mu1^2+mu2^2 = (mu_a^2+mu_b^2)/2,  mu1*mu2 = (mu_a^2-mu_b^2)/4,
//               E[p^2]+E[t^2] = (Ea+Eb)/2,        E[p*t]  = (Ea-Eb)/4.
// Block: 128 output cols x 64 output rows; 64 threads, each owns 2 adjacent
// columns packed into one f32x2 register pair.
// Raw rows streamed via double-buffered cp.async (zfill = SAME zero pad).
// Vertical conv: register-rolling 11-slot f32x2 accumulator ring (4 ch),
// warp-uniform guarded scatter (proven-best R4 structure).
// ---------------------------------------------------------------------------

#define IMG_H 512
#define IMG_W 512
#define NBATCH 32
#define THREADS 64
#define TW 128              // output cols per block
#define RH 64               // output rows per block
#define NIN (RH + 10)       // 74 input rows touched
#define RAWW 144            // staged row width in floats ([x0-8, x0+136))
#define NV4 (RAWW / 4)      // 36 float4 per row
#define GROUP 11
#define NGROUPS ((NIN + GROUP - 1) / GROUP)   // 7
#define NBLOCKS ((IMG_W / TW) * (IMG_H / RH) * NBATCH)   // 1024

using ull = unsigned long long;

__device__ double   g_accum = 0.0;
__device__ unsigned g_count = 0;

// ---- packed f32x2 helpers (sm_103a) ----
__device__ __forceinline__ ull pack2(float lo, float hi) {
    ull r; asm("mov.b64 %0, {%1, %2};" : "=l"(r) : "f"(lo), "f"(hi)); return r;
}
__device__ __forceinline__ ull fma2(ull a, ull b, ull c) {
    ull r; asm("fma.rn.f32x2 %0, %1, %2, %3;" : "=l"(r) : "l"(a), "l"(b), "l"(c)); return r;
}
__device__ __forceinline__ ull mul2(ull a, ull b) {
    ull r; asm("mul.rn.f32x2 %0, %1, %2;" : "=l"(r) : "l"(a), "l"(b)); return r;
}
__device__ __forceinline__ float2 unpk2(ull v) {
    float2 f; asm("mov.b64 {%0, %1}, %2;" : "=f"(f.x), "=f"(f.y) : "l"(v)); return f;
}

__device__ __forceinline__ unsigned smem_u32(const void* p) {
    return (unsigned)__cvta_generic_to_shared(p);
}
__device__ __forceinline__ void cp_async16(unsigned saddr, const void* gaddr, int srcsize) {
    asm volatile("cp.async.ca.shared.global [%0], [%1], 16, %2;\n"
                 :: "r"(saddr), "l"(gaddr), "r"(srcsize));
}
__device__ __forceinline__ void cp_commit() { asm volatile("cp.async.commit_group;\n" ::: "memory"); }
__device__ __forceinline__ void cp_wait1()  { asm volatile("cp.async.wait_group 1;\n" ::: "memory"); }
__device__ __forceinline__ void cp_wait0()  { asm volatile("cp.async.wait_group 0;\n" ::: "memory"); }

// Issue cp.async for one 11-row group of both tensors into sbuf.
__device__ __forceinline__ void load_group(float* sbuf,  // [2][GROUP][RAWW]
                                           const float* __restrict__ P,
                                           const float* __restrict__ T,
                                           int g, int x0, int y0) {
    const int total = 2 * GROUP * NV4;  // 792
    for (int idx = threadIdx.x; idx < total; idx += THREADS) {
        int tsel = idx / (GROUP * NV4);
        int rem  = idx % (GROUP * NV4);
        int r    = rem / NV4;
        int cv   = rem % NV4;
        int i    = g * GROUP + r;
        int ir   = y0 - 5 + i;
        int c0   = x0 - 8 + cv * 4;
        bool ok = (i < NIN) && ((unsigned)ir < (unsigned)IMG_H) && ((unsigned)c0 < (unsigned)IMG_W);
        const float* src = tsel ? T : P;
        const float* gp  = ok ? (src + (size_t)ir * IMG_W + c0) : src;
        unsigned sa = smem_u32(sbuf + (tsel * GROUP + r) * RAWW + cv * 4);
        cp_async16(sa, gp, ok ? 16 : 0);
    }
}

__global__ void __launch_bounds__(THREADS, 6)
ssim_main(const float* __restrict__ pred, const float* __restrict__ targ,
          float* __restrict__ out) {
    __shared__ __align__(16) float sraw[2][2][GROUP][RAWW];   // 24.75 KB
    __shared__ float sred[THREADS / 32];
    __shared__ bool amLast;

    const int x0 = blockIdx.x * TW;
    const int y0 = blockIdx.y * RH;
    const int b  = blockIdx.z;
    const float* P = pred + (size_t)b * (IMG_H * IMG_W);
    const float* T = targ + (size_t)b * (IMG_H * IMG_W);
    const int tid = threadIdx.x;

    // 1D Gaussian weights (normalized) as compile-time literals.
    const float Wc[11] = {
        1.4867195e-06f, 1.3383023e-04f, 4.4318484e-03f, 5.3990967e-02f,
        2.4197073e-01f, 3.9894228e-01f, 2.4197073e-01f, 5.3990967e-02f,
        4.4318484e-03f, 1.3383023e-04f, 1.4867195e-06f };
    const float C1f = 1e-4f;   // 0.01^2
    const float C2f = 9e-4f;   // 0.03^2

    // Packed (replicated) weights + packed +/-1, loop-invariant registers.
    ull W2[11];
    #pragma unroll
    for (int k = 0; k < 11; ++k) W2[k] = pack2(Wc[k], Wc[k]);
    const ull ONE2 = pack2(1.0f, 1.0f);
    const ull NEG2 = pack2(-1.0f, -1.0f);

    // Rolling vertical accumulators: 4 channels (a, b, a^2, b^2) x 11 slots.
    ull acc[4][GROUP];
    #pragma unroll
    for (int c = 0; c < 4; ++c)
        #pragma unroll
        for (int s = 0; s < GROUP; ++s) acc[c][s] = 0ull;

    float tsum = 0.f;

    // Prologue: prefetch group 0
    load_group(&sraw[0][0][0][0], P, T, 0, x0, y0);
    cp_commit();

    for (int g = 0; g < NGROUPS; ++g) {
        if (g + 1 < NGROUPS) {
            load_group(&sraw[(g + 1) & 1][0][0][0], P, T, g + 1, x0, y0);
            cp_commit();
            cp_wait1();     // group g complete, group g+1 may be in flight
        } else {
            cp_wait0();
        }
        __syncthreads();

        const float* basep = &sraw[g & 1][0][0][0];
        const float* baset = &sraw[g & 1][1][0][0];

        #pragma unroll
        for (int j = 0; j < GROUP; ++j) {
            int i = g * GROUP + j;
            if (i < NIN) {
                // ---- load aligned p/t pairs, form a = p+t, b = p-t ----
                ull Aa[7], Ab[7];
                float af[14], bf[14];
                #pragma unroll
                for (int m = 0; m < 7; ++m) {
                    ull Apm = *(const ull*)(basep + j * RAWW + 2 * tid + 2 + 2 * m);
                    ull Atm = *(const ull*)(baset + j * RAWW + 2 * tid + 2 + 2 * m);
                    Aa[m] = fma2(Atm, ONE2, Apm);   // p + t
                    Ab[m] = fma2(Atm, NEG2, Apm);   // p - t
                    float2 x = unpk2(Aa[m]); af[2 * m] = x.x; af[2 * m + 1] = x.y;
                    float2 y = unpk2(Ab[m]); bf[2 * m] = y.x; bf[2 * m + 1] = y.y;
                }

                // ---- horizontal conv over 4 channels (a, b, a^2, b^2) ----
                // tap k needs pair (x[k+1], x[k+2]); odd k hits an aligned pair.
                ull ha, hb, ha2, hb2;
                #pragma unroll
                for (int k = 0; k < 11; ++k) {
                    ull Aak, Abk;
                    if (k & 1) { Aak = Aa[(k + 1) / 2]; Abk = Ab[(k + 1) / 2]; }
                    else       { Aak = pack2(af[k + 1], af[k + 2]);
                                 Abk = pack2(bf[k + 1], bf[k + 2]); }
                    ull a2 = mul2(Aak, Aak);
                    ull b2 = mul2(Abk, Abk);
                    if (k == 0) {
                        ha  = mul2(Aak, W2[0]);
                        hb  = mul2(Abk, W2[0]);
                        ha2 = mul2(a2,  W2[0]);
                        hb2 = mul2(b2,  W2[0]);
                    } else {
                        ha  = fma2(Aak, W2[k], ha);
                        hb  = fma2(Abk, W2[k], hb);
                        ha2 = fma2(a2,  W2[k], ha2);
                        hb2 = fma2(b2,  W2[k], hb2);
                    }
                }
                ull h[4] = { ha, hb, ha2, hb2 };

                // ---- vertical scatter into rolling ring (warp-uniform guards) ----
                #pragma unroll
                for (int k = 0; k < 11; ++k) {
                    const int s = (j - k + 11) % 11;     // compile-time
                    bool on = (i >= k) && (i - k < RH);
                    if (on) {
                        #pragma unroll
                        for (int ch = 0; ch < 4; ++ch) {
                            if (k == 0) acc[ch][s] = mul2(h[ch], W2[0]);   // fresh slot
                            else        acc[ch][s] = fma2(h[ch], W2[k], acc[ch][s]);
                        }
                    }
                }

                // ---- finalize output row oy = i - 10 ----
                if (i >= 10) {
                    const int f = (j + 1) % 11;          // compile-time
                    float2 mav = unpk2(acc[0][f]);   // mu_a = mu1+mu2
                    float2 mbv = unpk2(acc[1][f]);   // mu_b = mu1-mu2
                    float2 eav = unpk2(acc[2][f]);   // E[(p+t)^2]
                    float2 ebv = unpk2(acc[3][f]);   // E[(p-t)^2]
                    float n[2], d[2];
                    #pragma unroll
                    for (int v = 0; v < 2; ++v) {
                        float ma = v ? mav.y : mav.x;
                        float mb = v ? mbv.y : mbv.x;
                        float ea = v ? eav.y : eav.x;
                        float eb = v ? ebv.y : ebv.x;
                        float m2a = ma * ma;
                        float m2b = mb * mb;
                        float mp = m2a + m2b;   // 2(mu1^2 + mu2^2)
                        float mm = m2a - m2b;   // 4 mu1 mu2
                        float ep = ea + eb;     // 2(E[p^2] + E[t^2])
                        float em = ea - eb;     // 4 E[pt]
                        // num = (2 mu12 + C1)(2 s12 + C2); den = (mu1^2+mu2^2+C1)(s1+s2+C2)
                        float num1 = fmaf(0.5f, mm, C1f);
                        float num2 = fmaf(0.5f, em - mm, C2f);
                        float den1 = fmaf(0.5f, mp, C1f);
                        float den2 = fmaf(0.5f, ep - mp, C2f);
                        n[v] = num1 * num2;
                        d[v] = den1 * den2;
                    }
                    // n0/d0 + n1/d1 = (n0*d1 + n1*d0) * rcp(d0*d1); d > C1*C2 > 0
                    float num = n[0] * d[1] + n[1] * d[0];
                    float rden;
                    asm("rcp.approx.f32 %0, %1;" : "=f"(rden) : "f"(d[0] * d[1]));
                    tsum = fmaf(num, rden, tsum);
                }
            }
        }
        __syncthreads();   // protect buffer (g&1) before next prefetch reuses it
    }

    // ---- block reduction -> global double accumulator ----
    float s = tsum;
    #pragma unroll
    for (int off = 16; off; off >>= 1)
        s += __shfl_xor_sync(0xffffffffu, s, off);
    if ((tid & 31) == 0) sred[tid >> 5] = s;
    __syncthreads();
    if (tid == 0) {
        atomicAdd(&g_accum, (double)(sred[0] + sred[1]));
        __threadfence();
        unsigned prev = atomicAdd(&g_count, 1u);
        amLast = (prev == (unsigned)(NBLOCKS - 1));
    }
    __syncthreads();

    // ---- last block finalizes and resets state for the next graph replay ----
    if (amLast && tid == 0) {
        double total = atomicAdd(&g_accum, 0.0);   // coherent read
        out[0] = (float)(1.0 - total * (1.0 / (double)(NBATCH * IMG_H * IMG_W)));
        g_accum = 0.0;
        g_count = 0u;
    }
}

extern "C" void kernel_launch(void* const* d_in, const int* in_sizes, int n_in,
                              void* d_out, int out_size) {
    const float* pred = (const float*)d_in[0];
    const float* targ = (const float*)d_in[1];
    // d_in[2] (window) is a fixed Gaussian; weights are baked as immediates.
    (void)in_sizes; (void)n_in; (void)out_size;

    dim3 grid(IMG_W / TW, IMG_H / RH, NBATCH);   // 4 x 8 x 32 = 1024 blocks
    ssim_main<<<grid, THREADS>>>(pred, targ, (float*)d_out);
}